// round 9
// baseline (speedup 1.0000x reference)
#include <cuda_runtime.h>
#include <cstdint>

// Kalman predict: x_hat = Ap x ; P_hat = Ap P Ap^T + Q,  Ap = triu(relu(A))
// Persistent warps, grid-stride over 32-batch tiles, double-buffered
// cp.async.cg pipeline: tile i+1 fills while tile i computes/stores, so each
// warp keeps DRAM reads continuously in flight. Buffers are warp-private
// (only __syncwarp needed). Padded smem rows (STRIDE=68) keep both the
// coalesced staging phase and the own-row compute phase bank-conflict-free.

#define BLOCK   64
#define WARPS   (BLOCK / 32)
#define BPW     32                 // batches per tile (1 per lane)
#define STRIDE  68                 // padded floats per batch row (64 + 4)
#define GRID    912                // ~6 blocks/SM persistent

__device__ __forceinline__ void cp_async16(unsigned int smem_addr, const void* gmem) {
    asm volatile("cp.async.cg.shared.global [%0], [%1], 16;"
                 :: "r"(smem_addr), "l"(gmem) : "memory");
}
__device__ __forceinline__ void cp_async_commit() {
    asm volatile("cp.async.commit_group;" ::: "memory");
}
__device__ __forceinline__ void cp_async_wait_1() {
    asm volatile("cp.async.wait_group 1;" ::: "memory");
}

// Issue the 16 cp.async float4 copies for one tile into one buffer.
__device__ __forceinline__ void stage_tile(const float* __restrict__ P,
                                           float* sb, int tileBase, int t, int B)
{
    const float4* src = reinterpret_cast<const float4*>(P) + (size_t)tileBase * 16;
    if (tileBase + BPW <= B) {
#pragma unroll
        for (int k = 0; k < 16; k++) {
            int g4 = t + 32 * k;
            int batch = g4 >> 4;
            int col   = (g4 & 15) << 2;
            unsigned int sa = (unsigned int)__cvta_generic_to_shared(&sb[batch * STRIDE + col]);
            cp_async16(sa, src + g4);
        }
    } else {
        const int lim4 = (B - tileBase) * 16;
#pragma unroll
        for (int k = 0; k < 16; k++) {
            int g4 = t + 32 * k;
            if (g4 < lim4) {
                int batch = g4 >> 4;
                int col   = (g4 & 15) << 2;
                unsigned int sa = (unsigned int)__cvta_generic_to_shared(&sb[batch * STRIDE + col]);
                cp_async16(sa, src + g4);
            }
        }
    }
}

__global__ void __launch_bounds__(BLOCK)
kf_predict_kernel(const float* __restrict__ x,
                  const float* __restrict__ P,
                  const float* __restrict__ A,
                  const float* __restrict__ sigma_p,
                  const float* __restrict__ sigma_v,
                  float* __restrict__ x_hat,
                  float* __restrict__ P_hat,
                  int B)
{
    __shared__ float sbuf[WARPS][2][BPW * STRIDE];   // 2*2*8704 B = 34816 B

    const int w = threadIdx.x >> 5;
    const int t = threadIdx.x & 31;
    const int warpId     = blockIdx.x * WARPS + w;
    const int totalWarps = gridDim.x * WARPS;
    const int numTiles   = (B + BPW - 1) / BPW;

    // ---- Ap = triu(relu(A)) : 16 uniform float4 loads, amortized over all tiles ----
    float ap[8][8];
    {
        const float4* A4 = reinterpret_cast<const float4*>(A);
#pragma unroll
        for (int i = 0; i < 8; i++) {
            float4 lo = __ldg(A4 + i * 2);
            float4 hi = __ldg(A4 + i * 2 + 1);
            float row[8] = {lo.x, lo.y, lo.z, lo.w, hi.x, hi.y, hi.z, hi.w};
#pragma unroll
            for (int j = 0; j < 8; j++)
                ap[i][j] = (j >= i) ? fmaxf(row[j], 0.0f) : 0.0f;
        }
    }
    const float sp = __ldg(sigma_p);
    const float sv = __ldg(sigma_v);

    if (warpId >= numTiles) return;

    // ---- prologue: fill buffer 0 with first tile ----
    stage_tile(P, sbuf[w][0], warpId * BPW, t, B);
    cp_async_commit();

    int cur = 0;
    for (int tile = warpId; tile < numTiles; tile += totalWarps, cur ^= 1) {
        const int tileBase = tile * BPW;
        const int b = tileBase + t;
        const bool valid = (b < B);
        float* sb = sbuf[w][cur];

        // ---- prefetch next tile into the other buffer ----
        const int nextTile = tile + totalWarps;
        if (nextTile < numTiles)
            stage_tile(P, sbuf[w][cur ^ 1], nextTile * BPW, t, B);
        cp_async_commit();   // always commit: keeps group count invariant

        // ---- overlap window: x load + x_hat while tile data lands ----
        float xv[8];
        {
            const int xb = valid ? b : (B - 1);
            const float4* x4 = reinterpret_cast<const float4*>(x + (size_t)xb * 8);
            float4 a0 = __ldg(x4 + 0);
            float4 a1 = __ldg(x4 + 1);
            xv[0] = a0.x; xv[1] = a0.y; xv[2] = a0.z; xv[3] = a0.w;
            xv[4] = a1.x; xv[5] = a1.y; xv[6] = a1.z; xv[7] = a1.w;
        }
        if (valid) {
            float xh[8];
#pragma unroll
            for (int i = 0; i < 8; i++) {
                float s = 0.0f;
#pragma unroll
                for (int j = 0; j < 8; j++)
                    if (j >= i) s = fmaf(ap[i][j], xv[j], s);
                xh[i] = s;
            }
            float4* o4 = reinterpret_cast<float4*>(x_hat + (size_t)b * 8);
            o4[0] = make_float4(xh[0], xh[1], xh[2], xh[3]);
            o4[1] = make_float4(xh[4], xh[5], xh[6], xh[7]);
        }

        // ---- wait: current tile complete (next tile may still be in flight) ----
        cp_async_wait_1();
        __syncwarp();

        // ---- read own batch row from smem (conflict-free, STRIDE=68) ----
        float p[8][8];
#pragma unroll
        for (int r = 0; r < 8; r++) {
            float4 lo = *reinterpret_cast<const float4*>(&sb[t * STRIDE + r * 8]);
            float4 hi = *reinterpret_cast<const float4*>(&sb[t * STRIDE + r * 8 + 4]);
            p[r][0] = lo.x; p[r][1] = lo.y; p[r][2] = lo.z; p[r][3] = lo.w;
            p[r][4] = hi.x; p[r][5] = hi.y; p[r][6] = hi.z; p[r][7] = hi.w;
        }

        // ---- stage 2 first (row-local): p[j] <- v_j, v_j[l] = sum_{k>=l} p[j][k]*ap[l][k] ----
#pragma unroll
        for (int j = 0; j < 8; j++) {
            float vrow[8];
#pragma unroll
            for (int l = 0; l < 8; l++) {
                float s = 0.0f;
#pragma unroll
                for (int k = 0; k < 8; k++)
                    if (k >= l) s = fmaf(p[j][k], ap[l][k], s);
                vrow[l] = s;
            }
#pragma unroll
            for (int l = 0; l < 8; l++) p[j][l] = vrow[l];
        }

        // ---- Q diagonal terms ----
        const float h  = xv[2];
        const float wd = xv[3];
        float dq[8];
        dq[0] = h * sp;  dq[1] = wd * sp;  dq[2] = h * sp;  dq[3] = wd * sp;
        dq[4] = h * sv;  dq[5] = wd * sv;  dq[6] = h * sv;  dq[7] = wd * sv;

        // ---- stage 1: o[i][l] = sum_{j>=i} ap[i][j] * v_j[l] ; rows -> smem ----
#pragma unroll
        for (int i = 0; i < 8; i++) {
            float orow[8];
#pragma unroll
            for (int l = 0; l < 8; l++) {
                float s = 0.0f;
#pragma unroll
                for (int j = 0; j < 8; j++)
                    if (j >= i) s = fmaf(ap[i][j], p[j][l], s);
                orow[l] = s;
            }
            orow[i] = fmaf(dq[i], dq[i], orow[i]);
            *reinterpret_cast<float4*>(&sb[t * STRIDE + i * 8]) =
                make_float4(orow[0], orow[1], orow[2], orow[3]);
            *reinterpret_cast<float4*>(&sb[t * STRIDE + i * 8 + 4]) =
                make_float4(orow[4], orow[5], orow[6], orow[7]);
        }
        __syncwarp();

        // ---- coalesced store of the tile to P_hat ----
        {
            float4* dst = reinterpret_cast<float4*>(P_hat) + (size_t)tileBase * 16;
            if (tileBase + BPW <= B) {
#pragma unroll
                for (int k = 0; k < 16; k++) {
                    int g4 = t + 32 * k;
                    int batch = g4 >> 4;
                    int col   = (g4 & 15) << 2;
                    dst[g4] = *reinterpret_cast<const float4*>(&sb[batch * STRIDE + col]);
                }
            } else {
                const int lim4 = (B - tileBase) * 16;
#pragma unroll
                for (int k = 0; k < 16; k++) {
                    int g4 = t + 32 * k;
                    if (g4 < lim4) {
                        int batch = g4 >> 4;
                        int col   = (g4 & 15) << 2;
                        dst[g4] = *reinterpret_cast<const float4*>(&sb[batch * STRIDE + col]);
                    }
                }
            }
        }
        __syncwarp();   // tile fully consumed before next iteration reuses this buffer
    }
}

extern "C" void kernel_launch(void* const* d_in, const int* in_sizes, int n_in,
                              void* d_out, int out_size)
{
    const float* x  = (const float*)d_in[0];   // (B, 8, 1)
    const float* P  = (const float*)d_in[1];   // (B, 8, 8)
    const float* A  = (const float*)d_in[2];   // (8, 8)
    const float* sp = (const float*)d_in[3];   // scalar
    const float* sv = (const float*)d_in[4];   // scalar

    const int B = in_sizes[0] / 8;

    float* out   = (float*)d_out;
    float* x_hat = out;                        // B*8 floats
    float* P_hat = out + (size_t)B * 8;        // B*64 floats

    const int numTiles = (B + BPW - 1) / BPW;
    int blocks = (numTiles + WARPS - 1) / WARPS;
    if (blocks > GRID) blocks = GRID;
    kf_predict_kernel<<<blocks, BLOCK>>>(x, P, A, sp, sv, x_hat, P_hat, B);
}

// round 10
// speedup vs baseline: 1.0426x; 1.0426x over previous
#include <cuda_runtime.h>
#include <cstdint>

// Kalman predict: x_hat = Ap x ; P_hat = Ap P Ap^T + Q,  Ap = triu(relu(A))
// R7 structure (best known): 1 thread per batch, per-warp smem staging with
// cp.async.cg overlap. R9 change: A lives in __constant__ memory (LDC via the
// constant port) instead of 16 per-thread LDG.128 — removes ~19% of the
// L1tex/LSU instruction stream, which is the binding resource at DRAM≈70%.

#define BLOCK   160
#define WARPS   (BLOCK / 32)
#define BPW     32                 // batches per warp
#define STRIDE  68                 // padded floats per batch row (64 + 4)

__constant__ float cA[64];

__device__ __forceinline__ void cp_async16(unsigned int smem_addr, const void* gmem) {
    asm volatile("cp.async.cg.shared.global [%0], [%1], 16;"
                 :: "r"(smem_addr), "l"(gmem) : "memory");
}
__device__ __forceinline__ void cp_async_commit() {
    asm volatile("cp.async.commit_group;" ::: "memory");
}
__device__ __forceinline__ void cp_async_wait_all() {
    asm volatile("cp.async.wait_group 0;" ::: "memory");
}

__global__ void __launch_bounds__(BLOCK)
kf_predict_kernel(const float* __restrict__ x,
                  const float* __restrict__ P,
                  const float* __restrict__ sigma_p,
                  const float* __restrict__ sigma_v,
                  float* __restrict__ x_hat,
                  float* __restrict__ P_hat,
                  int B)
{
    __shared__ float sbuf[WARPS][BPW * STRIDE];   // 5 * 8704 B = 43520 B

    const int w = threadIdx.x >> 5;
    const int t = threadIdx.x & 31;
    const int warpBatch0 = (blockIdx.x * WARPS + w) * BPW;
    if (warpBatch0 >= B) return;                  // whole-warp uniform exit
    const int b = warpBatch0 + t;                 // this thread's batch
    const bool fullWarp = (warpBatch0 + BPW <= B);
    const bool valid = (b < B);

    float* sb = sbuf[w];

    // ---- kick off async staging of this warp's 32 batches of P ----
    {
        const float4* src = reinterpret_cast<const float4*>(P) + (size_t)warpBatch0 * 16;
        if (fullWarp) {
#pragma unroll
            for (int k = 0; k < 16; k++) {
                int g4 = t + 32 * k;
                int batch = g4 >> 4;
                int col   = (g4 & 15) << 2;
                unsigned int sa = (unsigned int)__cvta_generic_to_shared(&sb[batch * STRIDE + col]);
                cp_async16(sa, src + g4);
            }
        } else {
            const int lim4 = (B - warpBatch0) * 16; // valid float4s in this tile
#pragma unroll
            for (int k = 0; k < 16; k++) {
                int g4 = t + 32 * k;
                if (g4 < lim4) {
                    int batch = g4 >> 4;
                    int col   = (g4 & 15) << 2;
                    unsigned int sa = (unsigned int)__cvta_generic_to_shared(&sb[batch * STRIDE + col]);
                    cp_async16(sa, src + g4);
                }
            }
        }
        cp_async_commit();
    }

    // ---- Ap = triu(relu(A)) from constant memory (LDC, no L1tex traffic) ----
    float ap[8][8];
#pragma unroll
    for (int i = 0; i < 8; i++) {
#pragma unroll
        for (int j = 0; j < 8; j++)
            ap[i][j] = (j >= i) ? fmaxf(cA[i * 8 + j], 0.0f) : 0.0f;
    }
    const float sp = __ldg(sigma_p);
    const float sv = __ldg(sigma_v);

    // ---- x: direct per-thread load (overlaps the async P fill) ----
    float xv[8];
    {
        const int xb = valid ? b : (B - 1);
        const float4* x4 = reinterpret_cast<const float4*>(x + (size_t)xb * 8);
        float4 a0 = __ldg(x4 + 0);
        float4 a1 = __ldg(x4 + 1);
        xv[0] = a0.x; xv[1] = a0.y; xv[2] = a0.z; xv[3] = a0.w;
        xv[4] = a1.x; xv[5] = a1.y; xv[6] = a1.z; xv[7] = a1.w;
    }

    // ---- x_hat = Ap x (still overlapping the async fill) ----
    if (valid) {
        float xh[8];
#pragma unroll
        for (int i = 0; i < 8; i++) {
            float s = 0.0f;
#pragma unroll
            for (int j = 0; j < 8; j++)
                if (j >= i) s = fmaf(ap[i][j], xv[j], s);
            xh[i] = s;
        }
        float4* o4 = reinterpret_cast<float4*>(x_hat + (size_t)b * 8);
        o4[0] = make_float4(xh[0], xh[1], xh[2], xh[3]);
        o4[1] = make_float4(xh[4], xh[5], xh[6], xh[7]);
    }

    // ---- wait for P tile, then read own batch row (conflict-free, STRIDE=68) ----
    cp_async_wait_all();
    __syncwarp();

    float p[8][8];
#pragma unroll
    for (int r = 0; r < 8; r++) {
        float4 lo = *reinterpret_cast<const float4*>(&sb[t * STRIDE + r * 8]);
        float4 hi = *reinterpret_cast<const float4*>(&sb[t * STRIDE + r * 8 + 4]);
        p[r][0] = lo.x; p[r][1] = lo.y; p[r][2] = lo.z; p[r][3] = lo.w;
        p[r][4] = hi.x; p[r][5] = hi.y; p[r][6] = hi.z; p[r][7] = hi.w;
    }

    // ---- stage 2 first (row-local): p[j] <- v_j, v_j[l] = sum_{k>=l} p[j][k]*ap[l][k] ----
#pragma unroll
    for (int j = 0; j < 8; j++) {
        float vrow[8];
#pragma unroll
        for (int l = 0; l < 8; l++) {
            float s = 0.0f;
#pragma unroll
            for (int k = 0; k < 8; k++)
                if (k >= l) s = fmaf(p[j][k], ap[l][k], s);
            vrow[l] = s;
        }
#pragma unroll
        for (int l = 0; l < 8; l++) p[j][l] = vrow[l];
    }

    // ---- Q diagonal terms ----
    const float h  = xv[2];
    const float wd = xv[3];
    float dq[8];
    dq[0] = h * sp;  dq[1] = wd * sp;  dq[2] = h * sp;  dq[3] = wd * sp;
    dq[4] = h * sv;  dq[5] = wd * sv;  dq[6] = h * sv;  dq[7] = wd * sv;

    // ---- stage 1: o[i][l] = sum_{j>=i} ap[i][j] * v_j[l] ; rows -> smem ----
#pragma unroll
    for (int i = 0; i < 8; i++) {
        float orow[8];
#pragma unroll
        for (int l = 0; l < 8; l++) {
            float s = 0.0f;
#pragma unroll
            for (int j = 0; j < 8; j++)
                if (j >= i) s = fmaf(ap[i][j], p[j][l], s);
            orow[l] = s;
        }
        orow[i] = fmaf(dq[i], dq[i], orow[i]);
        *reinterpret_cast<float4*>(&sb[t * STRIDE + i * 8]) =
            make_float4(orow[0], orow[1], orow[2], orow[3]);
        *reinterpret_cast<float4*>(&sb[t * STRIDE + i * 8 + 4]) =
            make_float4(orow[4], orow[5], orow[6], orow[7]);
    }
    __syncwarp();

    // ---- coalesced store of the warp tile to P_hat ----
    {
        float4* dst = reinterpret_cast<float4*>(P_hat) + (size_t)warpBatch0 * 16;
        if (fullWarp) {
#pragma unroll
            for (int k = 0; k < 16; k++) {
                int g4 = t + 32 * k;
                int batch = g4 >> 4;
                int col   = (g4 & 15) << 2;
                dst[g4] = *reinterpret_cast<const float4*>(&sb[batch * STRIDE + col]);
            }
        } else {
            const int lim4 = (B - warpBatch0) * 16;
#pragma unroll
            for (int k = 0; k < 16; k++) {
                int g4 = t + 32 * k;
                if (g4 < lim4) {
                    int batch = g4 >> 4;
                    int col   = (g4 & 15) << 2;
                    dst[g4] = *reinterpret_cast<const float4*>(&sb[batch * STRIDE + col]);
                }
            }
        }
    }
}

extern "C" void kernel_launch(void* const* d_in, const int* in_sizes, int n_in,
                              void* d_out, int out_size)
{
    const float* x  = (const float*)d_in[0];   // (B, 8, 1)
    const float* P  = (const float*)d_in[1];   // (B, 8, 8)
    const float* A  = (const float*)d_in[2];   // (8, 8)
    const float* sp = (const float*)d_in[3];   // scalar
    const float* sv = (const float*)d_in[4];   // scalar

    const int B = in_sizes[0] / 8;

    // A (256 B) -> constant memory; D2D async copy is graph-capturable.
    cudaMemcpyToSymbolAsync(cA, A, 64 * sizeof(float), 0,
                            cudaMemcpyDeviceToDevice, 0);

    float* out   = (float*)d_out;
    float* x_hat = out;                        // B*8 floats
    float* P_hat = out + (size_t)B * 8;        // B*64 floats

    const int batchesPerBlock = WARPS * BPW;   // 160
    const int blocks = (B + batchesPerBlock - 1) / batchesPerBlock;
    kf_predict_kernel<<<blocks, BLOCK>>>(x, P, sp, sv, x_hat, P_hat, B);
}

// round 11
// speedup vs baseline: 1.0860x; 1.0417x over previous
#include <cuda_runtime.h>
#include <cstdint>

// Kalman predict: x_hat = Ap x ; P_hat = Ap P Ap^T + Q,  Ap = triu(relu(A))
// R7 structure (best known: 47.9us bench / 41.9us kernel): 1 thread per batch,
// per-warp smem staging, cp.async.cg overlap of the x/x_hat path with the P
// tile fill. R10 change: streaming (evict-first) store hints __stcs on the
// write-once output stream, __ldcs on x reads — keeps L2 from holding
// dead lines so the DRAM scheduler favors the read stream.

#define BLOCK   160
#define WARPS   (BLOCK / 32)
#define BPW     32                 // batches per warp
#define STRIDE  68                 // padded floats per batch row (64 + 4)

__device__ __forceinline__ void cp_async16(unsigned int smem_addr, const void* gmem) {
    asm volatile("cp.async.cg.shared.global [%0], [%1], 16;"
                 :: "r"(smem_addr), "l"(gmem) : "memory");
}
__device__ __forceinline__ void cp_async_commit() {
    asm volatile("cp.async.commit_group;" ::: "memory");
}
__device__ __forceinline__ void cp_async_wait_all() {
    asm volatile("cp.async.wait_group 0;" ::: "memory");
}

__global__ void __launch_bounds__(BLOCK)
kf_predict_kernel(const float* __restrict__ x,
                  const float* __restrict__ P,
                  const float* __restrict__ A,
                  const float* __restrict__ sigma_p,
                  const float* __restrict__ sigma_v,
                  float* __restrict__ x_hat,
                  float* __restrict__ P_hat,
                  int B)
{
    __shared__ float sbuf[WARPS][BPW * STRIDE];   // 5 * 8704 B = 43520 B

    const int w = threadIdx.x >> 5;
    const int t = threadIdx.x & 31;
    const int warpBatch0 = (blockIdx.x * WARPS + w) * BPW;
    if (warpBatch0 >= B) return;                  // whole-warp uniform exit
    const int b = warpBatch0 + t;                 // this thread's batch
    const bool fullWarp = (warpBatch0 + BPW <= B);
    const bool valid = (b < B);

    float* sb = sbuf[w];

    // ---- kick off async staging of this warp's 32 batches of P ----
    {
        const float4* src = reinterpret_cast<const float4*>(P) + (size_t)warpBatch0 * 16;
        if (fullWarp) {
#pragma unroll
            for (int k = 0; k < 16; k++) {
                int g4 = t + 32 * k;
                int batch = g4 >> 4;
                int col   = (g4 & 15) << 2;
                unsigned int sa = (unsigned int)__cvta_generic_to_shared(&sb[batch * STRIDE + col]);
                cp_async16(sa, src + g4);
            }
        } else {
            const int lim4 = (B - warpBatch0) * 16; // valid float4s in this tile
#pragma unroll
            for (int k = 0; k < 16; k++) {
                int g4 = t + 32 * k;
                if (g4 < lim4) {
                    int batch = g4 >> 4;
                    int col   = (g4 & 15) << 2;
                    unsigned int sa = (unsigned int)__cvta_generic_to_shared(&sb[batch * STRIDE + col]);
                    cp_async16(sa, src + g4);
                }
            }
        }
        cp_async_commit();
    }

    // ---- Ap = triu(relu(A)) : 16 uniform float4 loads (L1-resident) ----
    float ap[8][8];
    {
        const float4* A4 = reinterpret_cast<const float4*>(A);
#pragma unroll
        for (int i = 0; i < 8; i++) {
            float4 lo = __ldg(A4 + i * 2);
            float4 hi = __ldg(A4 + i * 2 + 1);
            float row[8] = {lo.x, lo.y, lo.z, lo.w, hi.x, hi.y, hi.z, hi.w};
#pragma unroll
            for (int j = 0; j < 8; j++)
                ap[i][j] = (j >= i) ? fmaxf(row[j], 0.0f) : 0.0f;
        }
    }
    const float sp = __ldg(sigma_p);
    const float sv = __ldg(sigma_v);

    // ---- x: streaming per-thread load (overlaps the async P fill) ----
    float xv[8];
    {
        const int xb = valid ? b : (B - 1);
        const float4* x4 = reinterpret_cast<const float4*>(x + (size_t)xb * 8);
        float4 a0 = __ldcs(x4 + 0);
        float4 a1 = __ldcs(x4 + 1);
        xv[0] = a0.x; xv[1] = a0.y; xv[2] = a0.z; xv[3] = a0.w;
        xv[4] = a1.x; xv[5] = a1.y; xv[6] = a1.z; xv[7] = a1.w;
    }

    // ---- x_hat = Ap x (still overlapping the async fill), streaming store ----
    if (valid) {
        float xh[8];
#pragma unroll
        for (int i = 0; i < 8; i++) {
            float s = 0.0f;
#pragma unroll
            for (int j = 0; j < 8; j++)
                if (j >= i) s = fmaf(ap[i][j], xv[j], s);
            xh[i] = s;
        }
        float4* o4 = reinterpret_cast<float4*>(x_hat + (size_t)b * 8);
        __stcs(o4 + 0, make_float4(xh[0], xh[1], xh[2], xh[3]));
        __stcs(o4 + 1, make_float4(xh[4], xh[5], xh[6], xh[7]));
    }

    // ---- wait for P tile, then read own batch row (conflict-free, STRIDE=68) ----
    cp_async_wait_all();
    __syncwarp();

    float p[8][8];
#pragma unroll
    for (int r = 0; r < 8; r++) {
        float4 lo = *reinterpret_cast<const float4*>(&sb[t * STRIDE + r * 8]);
        float4 hi = *reinterpret_cast<const float4*>(&sb[t * STRIDE + r * 8 + 4]);
        p[r][0] = lo.x; p[r][1] = lo.y; p[r][2] = lo.z; p[r][3] = lo.w;
        p[r][4] = hi.x; p[r][5] = hi.y; p[r][6] = hi.z; p[r][7] = hi.w;
    }

    // ---- stage 2 first (row-local): p[j] <- v_j, v_j[l] = sum_{k>=l} p[j][k]*ap[l][k] ----
#pragma unroll
    for (int j = 0; j < 8; j++) {
        float vrow[8];
#pragma unroll
        for (int l = 0; l < 8; l++) {
            float s = 0.0f;
#pragma unroll
            for (int k = 0; k < 8; k++)
                if (k >= l) s = fmaf(p[j][k], ap[l][k], s);
            vrow[l] = s;
        }
#pragma unroll
        for (int l = 0; l < 8; l++) p[j][l] = vrow[l];
    }

    // ---- Q diagonal terms ----
    const float h  = xv[2];
    const float wd = xv[3];
    float dq[8];
    dq[0] = h * sp;  dq[1] = wd * sp;  dq[2] = h * sp;  dq[3] = wd * sp;
    dq[4] = h * sv;  dq[5] = wd * sv;  dq[6] = h * sv;  dq[7] = wd * sv;

    // ---- stage 1: o[i][l] = sum_{j>=i} ap[i][j] * v_j[l] ; rows -> smem ----
#pragma unroll
    for (int i = 0; i < 8; i++) {
        float orow[8];
#pragma unroll
        for (int l = 0; l < 8; l++) {
            float s = 0.0f;
#pragma unroll
            for (int j = 0; j < 8; j++)
                if (j >= i) s = fmaf(ap[i][j], p[j][l], s);
            orow[l] = s;
        }
        orow[i] = fmaf(dq[i], dq[i], orow[i]);
        *reinterpret_cast<float4*>(&sb[t * STRIDE + i * 8]) =
            make_float4(orow[0], orow[1], orow[2], orow[3]);
        *reinterpret_cast<float4*>(&sb[t * STRIDE + i * 8 + 4]) =
            make_float4(orow[4], orow[5], orow[6], orow[7]);
    }
    __syncwarp();

    // ---- coalesced streaming store of the warp tile to P_hat ----
    {
        float4* dst = reinterpret_cast<float4*>(P_hat) + (size_t)warpBatch0 * 16;
        if (fullWarp) {
#pragma unroll
            for (int k = 0; k < 16; k++) {
                int g4 = t + 32 * k;
                int batch = g4 >> 4;
                int col   = (g4 & 15) << 2;
                __stcs(dst + g4, *reinterpret_cast<const float4*>(&sb[batch * STRIDE + col]));
            }
        } else {
            const int lim4 = (B - warpBatch0) * 16;
#pragma unroll
            for (int k = 0; k < 16; k++) {
                int g4 = t + 32 * k;
                if (g4 < lim4) {
                    int batch = g4 >> 4;
                    int col   = (g4 & 15) << 2;
                    __stcs(dst + g4, *reinterpret_cast<const float4*>(&sb[batch * STRIDE + col]));
                }
            }
        }
    }
}

extern "C" void kernel_launch(void* const* d_in, const int* in_sizes, int n_in,
                              void* d_out, int out_size)
{
    const float* x  = (const float*)d_in[0];   // (B, 8, 1)
    const float* P  = (const float*)d_in[1];   // (B, 8, 8)
    const float* A  = (const float*)d_in[2];   // (8, 8)
    const float* sp = (const float*)d_in[3];   // scalar
    const float* sv = (const float*)d_in[4];   // scalar

    const int B = in_sizes[0] / 8;

    float* out   = (float*)d_out;
    float* x_hat = out;                        // B*8 floats
    float* P_hat = out + (size_t)B * 8;        // B*64 floats

    const int batchesPerBlock = WARPS * BPW;   // 160
    const int blocks = (B + batchesPerBlock - 1) / batchesPerBlock;
    kf_predict_kernel<<<blocks, BLOCK>>>(x, P, A, sp, sv, x_hat, P_hat, B);
}